// round 4
// baseline (speedup 1.0000x reference)
#include <cuda_runtime.h>
#include <math.h>

#define NNODE 94
#define MAXB  16384
#define NOUT  6400

// Scratch (device globals — no allocation allowed in kernel_launch)
__device__ float g_A  [NNODE * NNODE];   // dense normalized adjacency, A[dst][src]
__device__ float g_Ht [NNODE * MAXB];    // H transposed: g_Ht[k*B + b]
__device__ float g_WT [NNODE * NOUT];    // Wfc transposed: g_WT[k*6400 + n]

// ---------------------------------------------------------------------------
// Kernel 1: build dense normalized adjacency (single block)
// A[dst][src] = dinv[src] * w * dinv[dst], self-loops weight 1.
// ---------------------------------------------------------------------------
__global__ void build_graph_kernel(const int* __restrict__ ei,
                                   const float* __restrict__ ew, int E) {
    __shared__ float deg[NNODE];
    __shared__ float dinv[NNODE];
    int t = threadIdx.x;
    for (int i = t; i < NNODE; i += blockDim.x) deg[i] = 1.0f;  // self loop
    __syncthreads();
    for (int e = t; e < E; e += blockDim.x)
        atomicAdd(&deg[ei[E + e]], ew[e]);                      // dst row of edge_index
    __syncthreads();
    for (int i = t; i < NNODE; i += blockDim.x)
        dinv[i] = (deg[i] > 0.0f) ? rsqrtf(deg[i]) : 0.0f;
    for (int i = t; i < NNODE * NNODE; i += blockDim.x) g_A[i] = 0.0f;
    __syncthreads();
    for (int e = t; e < E; e += blockDim.x) {
        int s = ei[e];
        int d = ei[E + e];
        atomicAdd(&g_A[d * NNODE + s], dinv[s] * ew[e] * dinv[d]);
    }
    for (int i = t; i < NNODE; i += blockDim.x)
        atomicAdd(&g_A[i * NNODE + i], dinv[i] * dinv[i]);
}

// ---------------------------------------------------------------------------
// Kernel 2: transpose Wfc [6400,94] -> g_WT [94,6400]
// ---------------------------------------------------------------------------
__global__ void transpose_w_kernel(const float* __restrict__ Wfc) {
    int idx = blockIdx.x * blockDim.x + threadIdx.x;
    if (idx < NOUT * NNODE) {
        int n = idx / NNODE;
        int k = idx - n * NNODE;
        g_WT[k * NOUT + n] = Wfc[idx];
    }
}

// ---------------------------------------------------------------------------
// Kernel 3: GCN stage. Per batch element b:
//   xw = X W1; h1 = tanh(A xw + b1); z = h1 W2; H[b] = tanh(A z + b2)
// Writes H transposed into g_Ht[k*B + b].
// One block handles `bpb` consecutive batch elements; A cached in smem.
// ---------------------------------------------------------------------------
__global__ void stage1_kernel(const float* __restrict__ feat,
                              const float* __restrict__ W1,
                              const float* __restrict__ b1,
                              const float* __restrict__ W2,
                              const float* __restrict__ b2,
                              int B, int bpb) {
    __shared__ float As[NNODE * NNODE];
    __shared__ float xw[6][NNODE];
    __shared__ float h1v[NNODE];
    __shared__ float fbuf[NNODE * 3];
    __shared__ float w1s[18], b1s[6], w2s[6], b2s;

    int t = threadIdx.x;
    for (int i = t; i < NNODE * NNODE; i += blockDim.x) As[i] = g_A[i];
    if (t < 18) w1s[t] = W1[t];
    if (t < 6)  { b1s[t] = b1[t]; w2s[t] = W2[t]; }
    if (t == 0) b2s = b2[0];
    __syncthreads();

    for (int bb = 0; bb < bpb; bb++) {
        int b = blockIdx.x * bpb + bb;
        if (b >= B) return;  // uniform across block

        for (int i = t; i < NNODE * 3; i += blockDim.x)
            fbuf[i] = feat[b * (NNODE * 3) + i];
        __syncthreads();

        if (t < NNODE) {
            float x0 = fbuf[t * 3 + 0], x1 = fbuf[t * 3 + 1], x2 = fbuf[t * 3 + 2];
            #pragma unroll
            for (int c = 0; c < 6; c++)
                xw[c][t] = x0 * w1s[c] + x1 * w1s[6 + c] + x2 * w1s[12 + c];
        }
        __syncthreads();

        float hz = 0.0f;
        if (t < NNODE) {
            float acc[6] = {0, 0, 0, 0, 0, 0};
            for (int j = 0; j < NNODE; j++) {
                float a = As[t * NNODE + j];
                #pragma unroll
                for (int c = 0; c < 6; c++) acc[c] += a * xw[c][j];
            }
            #pragma unroll
            for (int c = 0; c < 6; c++)
                hz += tanhf(acc[c] + b1s[c]) * w2s[c];
        }
        __syncthreads();
        if (t < NNODE) h1v[t] = hz;
        __syncthreads();

        if (t < NNODE) {
            float acc = 0.0f;
            for (int j = 0; j < NNODE; j++) acc += As[t * NNODE + j] * h1v[j];
            g_Ht[t * B + b] = tanhf(acc + b2s);
        }
        __syncthreads();
    }
}

// ---------------------------------------------------------------------------
// Kernel 4: FC GEMM.  out[m][n] = sum_k Ht[k][m] * WT[k][n] + bfc[n]
// 128x128 block tile, full K strip (94 padded to 96) in smem, 8x8 per thread
// with 4+4 split fragments for conflict-free LDS.128.
// ---------------------------------------------------------------------------
#define BM 128
#define BN 128
#define BK 96

__global__ void __launch_bounds__(256, 2)
fc_gemm_kernel(const float* __restrict__ bfc, float* __restrict__ out, int B) {
    extern __shared__ float sm[];
    float* Hs = sm;             // [BK][BM]
    float* Ws = sm + BK * BM;   // [BK][BN]

    const int tid = threadIdx.x;
    const int m0 = blockIdx.y * BM;
    const int n0 = blockIdx.x * BN;

    // Load tiles (k-major global => coalesced, conflict-free smem writes)
    for (int i = tid; i < BK * BM; i += 256) {
        int k = i >> 7, m = i & 127;
        Hs[i] = (k < NNODE && (m0 + m) < B) ? g_Ht[k * B + m0 + m] : 0.0f;
    }
    for (int i = tid; i < BK * BN; i += 256) {
        int k = i >> 7, n = i & 127;
        Ws[i] = (k < NNODE) ? g_WT[k * NOUT + n0 + n] : 0.0f;
    }
    __syncthreads();

    const int tm = (tid & 15) * 4;   // m fragment base (and +64)
    const int tn = (tid >> 4) * 4;   // n fragment base (and +64)

    float acc[8][8];
    #pragma unroll
    for (int i = 0; i < 8; i++)
        #pragma unroll
        for (int j = 0; j < 8; j++) acc[i][j] = 0.0f;

    #pragma unroll 4
    for (int k = 0; k < BK; k++) {
        float4 a0 = *(const float4*)(Hs + k * BM + tm);
        float4 a1 = *(const float4*)(Hs + k * BM + 64 + tm);
        float4 c0 = *(const float4*)(Ws + k * BN + tn);
        float4 c1 = *(const float4*)(Ws + k * BN + 64 + tn);
        float av[8] = {a0.x, a0.y, a0.z, a0.w, a1.x, a1.y, a1.z, a1.w};
        float bv[8] = {c0.x, c0.y, c0.z, c0.w, c1.x, c1.y, c1.z, c1.w};
        #pragma unroll
        for (int i = 0; i < 8; i++)
            #pragma unroll
            for (int j = 0; j < 8; j++)
                acc[i][j] += av[i] * bv[j];
    }

    float bias[8];
    #pragma unroll
    for (int j = 0; j < 8; j++) {
        int n = n0 + ((j < 4) ? (tn + j) : (64 + tn + j - 4));
        bias[j] = bfc[n];
    }

    #pragma unroll
    for (int i = 0; i < 8; i++) {
        int m = m0 + ((i < 4) ? (tm + i) : (64 + tm + i - 4));
        if (m >= B) continue;
        float4 o0 = make_float4(acc[i][0] + bias[0], acc[i][1] + bias[1],
                                acc[i][2] + bias[2], acc[i][3] + bias[3]);
        float4 o1 = make_float4(acc[i][4] + bias[4], acc[i][5] + bias[5],
                                acc[i][6] + bias[6], acc[i][7] + bias[7]);
        *(float4*)(out + (size_t)m * NOUT + n0 + tn)      = o0;
        *(float4*)(out + (size_t)m * NOUT + n0 + 64 + tn) = o1;
    }
}

// ---------------------------------------------------------------------------
// Launch
// ---------------------------------------------------------------------------
extern "C" void kernel_launch(void* const* d_in, const int* in_sizes, int n_in,
                              void* d_out, int out_size) {
    const float* feature = (const float*)d_in[0];
    const int*   ei      = (const int*)  d_in[1];
    const float* ew      = (const float*)d_in[2];
    const float* W1      = (const float*)d_in[3];
    const float* b1      = (const float*)d_in[4];
    const float* W2      = (const float*)d_in[5];
    const float* b2      = (const float*)d_in[6];
    const float* Wfc     = (const float*)d_in[7];
    const float* bfc     = (const float*)d_in[8];
    float*       out     = (float*)d_out;

    const int B = in_sizes[0] / (NNODE * 3);
    const int E = in_sizes[1] / 2;

    build_graph_kernel<<<1, 256>>>(ei, ew, E);
    transpose_w_kernel<<<(NOUT * NNODE + 255) / 256, 256>>>(Wfc);

    const int grid1 = 2048;
    const int bpb = (B + grid1 - 1) / grid1;
    stage1_kernel<<<grid1, 128>>>(feature, W1, b1, W2, b2, B, bpb);

    cudaFuncSetAttribute(fc_gemm_kernel,
                         cudaFuncAttributeMaxDynamicSharedMemorySize,
                         2 * BK * BM * (int)sizeof(float));
    dim3 grid(NOUT / BN, (B + BM - 1) / BM);
    fc_gemm_kernel<<<grid, 256, 2 * BK * BM * sizeof(float)>>>(bfc, out, B);
}

// round 5
// speedup vs baseline: 1.0013x; 1.0013x over previous
#include <cuda_runtime.h>
#include <math.h>

#define NNODE 94
#define MAXB  16384
#define NOUT  6400

// Scratch (device globals — no allocation allowed in kernel_launch)
__device__ float g_A  [NNODE * NNODE];   // dense normalized adjacency, A[dst][src]
__device__ float g_Ht [NNODE * MAXB];    // H transposed: g_Ht[k*B + b]
__device__ float g_WT [NNODE * NOUT];    // Wfc transposed: g_WT[k*6400 + n]

// ---------------------------------------------------------------------------
// Kernel 1: build dense normalized adjacency (single block)
// A[dst][src] = dinv[src] * w * dinv[dst], self-loops weight 1.
// ---------------------------------------------------------------------------
__global__ void build_graph_kernel(const int* __restrict__ ei,
                                   const float* __restrict__ ew, int E) {
    __shared__ float deg[NNODE];
    __shared__ float dinv[NNODE];
    int t = threadIdx.x;
    for (int i = t; i < NNODE; i += blockDim.x) deg[i] = 1.0f;  // self loop
    __syncthreads();
    for (int e = t; e < E; e += blockDim.x)
        atomicAdd(&deg[ei[E + e]], ew[e]);                      // dst row of edge_index
    __syncthreads();
    for (int i = t; i < NNODE; i += blockDim.x)
        dinv[i] = (deg[i] > 0.0f) ? rsqrtf(deg[i]) : 0.0f;
    for (int i = t; i < NNODE * NNODE; i += blockDim.x) g_A[i] = 0.0f;
    __syncthreads();
    for (int e = t; e < E; e += blockDim.x) {
        int s = ei[e];
        int d = ei[E + e];
        atomicAdd(&g_A[d * NNODE + s], dinv[s] * ew[e] * dinv[d]);
    }
    for (int i = t; i < NNODE; i += blockDim.x)
        atomicAdd(&g_A[i * NNODE + i], dinv[i] * dinv[i]);
}

// ---------------------------------------------------------------------------
// Kernel 2: transpose Wfc [6400,94] -> g_WT [94,6400]
// ---------------------------------------------------------------------------
__global__ void transpose_w_kernel(const float* __restrict__ Wfc) {
    int idx = blockIdx.x * blockDim.x + threadIdx.x;
    if (idx < NOUT * NNODE) {
        int n = idx / NNODE;
        int k = idx - n * NNODE;
        g_WT[k * NOUT + n] = Wfc[idx];
    }
}

// ---------------------------------------------------------------------------
// Kernel 3: GCN stage. Per batch element b:
//   xw = X W1; h1 = tanh(A xw + b1); z = h1 W2; H[b] = tanh(A z + b2)
// Writes H transposed into g_Ht[k*B + b].
// One block handles `bpb` consecutive batch elements; A cached in smem.
// ---------------------------------------------------------------------------
__global__ void stage1_kernel(const float* __restrict__ feat,
                              const float* __restrict__ W1,
                              const float* __restrict__ b1,
                              const float* __restrict__ W2,
                              const float* __restrict__ b2,
                              int B, int bpb) {
    __shared__ float As[NNODE * NNODE];
    __shared__ float xw[6][NNODE];
    __shared__ float h1v[NNODE];
    __shared__ float fbuf[NNODE * 3];
    __shared__ float w1s[18], b1s[6], w2s[6], b2s;

    int t = threadIdx.x;
    for (int i = t; i < NNODE * NNODE; i += blockDim.x) As[i] = g_A[i];
    if (t < 18) w1s[t] = W1[t];
    if (t < 6)  { b1s[t] = b1[t]; w2s[t] = W2[t]; }
    if (t == 0) b2s = b2[0];
    __syncthreads();

    for (int bb = 0; bb < bpb; bb++) {
        int b = blockIdx.x * bpb + bb;
        if (b >= B) return;  // uniform across block

        for (int i = t; i < NNODE * 3; i += blockDim.x)
            fbuf[i] = feat[b * (NNODE * 3) + i];
        __syncthreads();

        if (t < NNODE) {
            float x0 = fbuf[t * 3 + 0], x1 = fbuf[t * 3 + 1], x2 = fbuf[t * 3 + 2];
            #pragma unroll
            for (int c = 0; c < 6; c++)
                xw[c][t] = x0 * w1s[c] + x1 * w1s[6 + c] + x2 * w1s[12 + c];
        }
        __syncthreads();

        float hz = 0.0f;
        if (t < NNODE) {
            float acc[6] = {0, 0, 0, 0, 0, 0};
            for (int j = 0; j < NNODE; j++) {
                float a = As[t * NNODE + j];
                #pragma unroll
                for (int c = 0; c < 6; c++) acc[c] += a * xw[c][j];
            }
            #pragma unroll
            for (int c = 0; c < 6; c++)
                hz += tanhf(acc[c] + b1s[c]) * w2s[c];
        }
        __syncthreads();
        if (t < NNODE) h1v[t] = hz;
        __syncthreads();

        if (t < NNODE) {
            float acc = 0.0f;
            for (int j = 0; j < NNODE; j++) acc += As[t * NNODE + j] * h1v[j];
            g_Ht[t * B + b] = tanhf(acc + b2s);
        }
        __syncthreads();
    }
}

// ---------------------------------------------------------------------------
// Kernel 4: FC GEMM.  out[m][n] = sum_k Ht[k][m] * WT[k][n] + bfc[n]
// 128x128 block tile, full K strip (94 padded to 96) in smem, 8x8 per thread
// with 4+4 split fragments for conflict-free LDS.128.
// ---------------------------------------------------------------------------
#define BM 128
#define BN 128
#define BK 96

__global__ void __launch_bounds__(256, 2)
fc_gemm_kernel(const float* __restrict__ bfc, float* __restrict__ out, int B) {
    extern __shared__ float sm[];
    float* Hs = sm;             // [BK][BM]
    float* Ws = sm + BK * BM;   // [BK][BN]

    const int tid = threadIdx.x;
    const int m0 = blockIdx.y * BM;
    const int n0 = blockIdx.x * BN;

    // Load tiles (k-major global => coalesced, conflict-free smem writes)
    for (int i = tid; i < BK * BM; i += 256) {
        int k = i >> 7, m = i & 127;
        Hs[i] = (k < NNODE && (m0 + m) < B) ? g_Ht[k * B + m0 + m] : 0.0f;
    }
    for (int i = tid; i < BK * BN; i += 256) {
        int k = i >> 7, n = i & 127;
        Ws[i] = (k < NNODE) ? g_WT[k * NOUT + n0 + n] : 0.0f;
    }
    __syncthreads();

    const int tm = (tid & 15) * 4;   // m fragment base (and +64)
    const int tn = (tid >> 4) * 4;   // n fragment base (and +64)

    float acc[8][8];
    #pragma unroll
    for (int i = 0; i < 8; i++)
        #pragma unroll
        for (int j = 0; j < 8; j++) acc[i][j] = 0.0f;

    #pragma unroll 4
    for (int k = 0; k < BK; k++) {
        float4 a0 = *(const float4*)(Hs + k * BM + tm);
        float4 a1 = *(const float4*)(Hs + k * BM + 64 + tm);
        float4 c0 = *(const float4*)(Ws + k * BN + tn);
        float4 c1 = *(const float4*)(Ws + k * BN + 64 + tn);
        float av[8] = {a0.x, a0.y, a0.z, a0.w, a1.x, a1.y, a1.z, a1.w};
        float bv[8] = {c0.x, c0.y, c0.z, c0.w, c1.x, c1.y, c1.z, c1.w};
        #pragma unroll
        for (int i = 0; i < 8; i++)
            #pragma unroll
            for (int j = 0; j < 8; j++)
                acc[i][j] += av[i] * bv[j];
    }

    float bias[8];
    #pragma unroll
    for (int j = 0; j < 8; j++) {
        int n = n0 + ((j < 4) ? (tn + j) : (64 + tn + j - 4));
        bias[j] = bfc[n];
    }

    #pragma unroll
    for (int i = 0; i < 8; i++) {
        int m = m0 + ((i < 4) ? (tm + i) : (64 + tm + i - 4));
        if (m >= B) continue;
        float4 o0 = make_float4(acc[i][0] + bias[0], acc[i][1] + bias[1],
                                acc[i][2] + bias[2], acc[i][3] + bias[3]);
        float4 o1 = make_float4(acc[i][4] + bias[4], acc[i][5] + bias[5],
                                acc[i][6] + bias[6], acc[i][7] + bias[7]);
        *(float4*)(out + (size_t)m * NOUT + n0 + tn)      = o0;
        *(float4*)(out + (size_t)m * NOUT + n0 + 64 + tn) = o1;
    }
}

// ---------------------------------------------------------------------------
// Launch
// ---------------------------------------------------------------------------
extern "C" void kernel_launch(void* const* d_in, const int* in_sizes, int n_in,
                              void* d_out, int out_size) {
    const float* feature = (const float*)d_in[0];
    const int*   ei      = (const int*)  d_in[1];
    const float* ew      = (const float*)d_in[2];
    const float* W1      = (const float*)d_in[3];
    const float* b1      = (const float*)d_in[4];
    const float* W2      = (const float*)d_in[5];
    const float* b2      = (const float*)d_in[6];
    const float* Wfc     = (const float*)d_in[7];
    const float* bfc     = (const float*)d_in[8];
    float*       out     = (float*)d_out;

    const int B = in_sizes[0] / (NNODE * 3);
    const int E = in_sizes[1] / 2;

    build_graph_kernel<<<1, 256>>>(ei, ew, E);
    transpose_w_kernel<<<(NOUT * NNODE + 255) / 256, 256>>>(Wfc);

    const int grid1 = 2048;
    const int bpb = (B + grid1 - 1) / grid1;
    stage1_kernel<<<grid1, 128>>>(feature, W1, b1, W2, b2, B, bpb);

    cudaFuncSetAttribute(fc_gemm_kernel,
                         cudaFuncAttributeMaxDynamicSharedMemorySize,
                         2 * BK * BM * (int)sizeof(float));
    dim3 grid(NOUT / BN, (B + BM - 1) / BM);
    fc_gemm_kernel<<<grid, 256, 2 * BK * BM * sizeof(float)>>>(bfc, out, B);
}